// round 5
// baseline (speedup 1.0000x reference)
#include <cuda_runtime.h>
#include <cuda_bf16.h>
#include <stdint.h>

// Problem constants (from reference)
#define ENTITIES_N 100000
#define RELATIONS_N 1000
#define BATCH 1024
#define WIDTH (2 * ENTITIES_N + RELATIONS_N)   // 201000

// Scatter the 3 ones per row. 3072 total stores — trivially cheap.
__global__ void scatter_ones_kernel(const int* __restrict__ hID,
                                    const int* __restrict__ rID,
                                    const int* __restrict__ tID,
                                    float* __restrict__ out) {
    int idx = blockIdx.x * blockDim.x + threadIdx.x;   // 0 .. 3*BATCH-1
    if (idx >= 3 * BATCH) return;
    int row = idx / 3;
    int seg = idx - row * 3;
    long long base = (long long)row * WIDTH;
    int col;
    if (seg == 0)       col = hID[row];
    else if (seg == 1)  col = ENTITIES_N + rID[row];
    else                col = ENTITIES_N + RELATIONS_N + tID[row];
    out[base + col] = 1.0f;
}

extern "C" void kernel_launch(void* const* d_in, const int* in_sizes, int n_in,
                              void* d_out, int out_size) {
    // Inputs per metadata order: z (f32, unused), hID (i32), rID (i32), tID (i32)
    const int* hID = (const int*)d_in[1];
    const int* rID = (const int*)d_in[2];
    const int* tID = (const int*)d_in[3];
    float* out = (float*)d_out;

    // 1) Zero the 823 MB output at peak HBM write bandwidth.
    //    cudaMemsetAsync is graph-capturable (becomes a memset node).
    cudaMemsetAsync(out, 0, (size_t)out_size * sizeof(float), 0);

    // 2) Write the 3072 ones.
    scatter_ones_kernel<<<(3 * BATCH + 255) / 256, 256>>>(hID, rID, tID, out);
}

// round 6
// speedup vs baseline: 1.0414x; 1.0414x over previous
#include <cuda_runtime.h>
#include <cuda_bf16.h>
#include <stdint.h>

// Problem constants (from reference)
#define ENTITIES_N 100000
#define RELATIONS_N 1000
#define BATCH 1024
#define WIDTH (2 * ENTITIES_N + RELATIONS_N)   // 201000 floats/row
#define ROW_VEC (WIDTH / 4)                    // 50250 float4s/row (exact)

// Fused: zero-fill the row slice and drop in the ones inline.
// Grid: x = chunks of the row, y = row. Block 256 threads, each thread
// writes VPT float4s (block-strided, coalesced).
#define TPB 256
#define VPT 4
#define CHUNK (TPB * VPT)   // 1024 float4s per block

__global__ void __launch_bounds__(TPB)
fused_onehot_kernel(const int* __restrict__ hID,
                    const int* __restrict__ rID,
                    const int* __restrict__ tID,
                    float* __restrict__ out) {
    const int row = blockIdx.y;
    // Three one-columns for this row (L1-broadcast across the block).
    const int c0 = __ldg(&hID[row]);
    const int c1 = ENTITIES_N + __ldg(&rID[row]);
    const int c2 = ENTITIES_N + RELATIONS_N + __ldg(&tID[row]);

    float4* row_out = (float4*)(out + (long long)row * WIDTH);
    int j = blockIdx.x * CHUNK + threadIdx.x;

    #pragma unroll
    for (int it = 0; it < VPT; ++it, j += TPB) {
        if (j < ROW_VEC) {
            const int base = j * 4;            // first element col of this float4
            float4 v = make_float4(0.f, 0.f, 0.f, 0.f);
            int d;
            d = c0 - base;
            if ((unsigned)d < 4u) ((float*)&v)[d] = 1.0f;
            d = c1 - base;
            if ((unsigned)d < 4u) ((float*)&v)[d] = 1.0f;
            d = c2 - base;
            if ((unsigned)d < 4u) ((float*)&v)[d] = 1.0f;
            row_out[j] = v;
        }
    }
}

extern "C" void kernel_launch(void* const* d_in, const int* in_sizes, int n_in,
                              void* d_out, int out_size) {
    // Inputs per metadata order: z (f32, unused), hID (i32), rID (i32), tID (i32)
    const int* hID = (const int*)d_in[1];
    const int* rID = (const int*)d_in[2];
    const int* tID = (const int*)d_in[3];
    float* out = (float*)d_out;

    dim3 grid((ROW_VEC + CHUNK - 1) / CHUNK, BATCH);  // (50, 1024)
    fused_onehot_kernel<<<grid, TPB>>>(hID, rID, tID, out);
}

// round 7
// speedup vs baseline: 1.0429x; 1.0014x over previous
#include <cuda_runtime.h>
#include <cuda_bf16.h>
#include <stdint.h>

// Problem constants (from reference)
#define ENTITIES_N 100000
#define RELATIONS_N 1000
#define BATCH 1024
#define WIDTH (2 * ENTITIES_N + RELATIONS_N)   // 201000 floats/row
#define ROW_VEC (WIDTH / 4)                    // 50250 float4s/row (exact)

#define TPB 256
#define VPT 8
#define CHUNK (TPB * VPT)   // 2048 float4s (8192 floats) per block

// Streaming 128-bit store (evict-first: data is write-once, never re-read).
__device__ __forceinline__ void stcs4(float4* p, float4 v) {
    asm volatile("st.global.cs.v4.f32 [%0], {%1, %2, %3, %4};"
                 :: "l"(p), "f"(v.x), "f"(v.y), "f"(v.z), "f"(v.w) : "memory");
}

__global__ void __launch_bounds__(TPB)
fused_onehot_kernel(const int* __restrict__ hID,
                    const int* __restrict__ rID,
                    const int* __restrict__ tID,
                    float* __restrict__ out) {
    const int row = blockIdx.y;
    const int c0 = __ldg(&hID[row]);
    const int c1 = ENTITIES_N + __ldg(&rID[row]);
    const int c2 = ENTITIES_N + RELATIONS_N + __ldg(&tID[row]);

    float4* row_out = (float4*)(out + (long long)row * WIDTH);
    const int chunk_lo = blockIdx.x * CHUNK;          // first float4 idx of block
    const int col_lo   = chunk_lo * 4;                // first element col
    const int col_hi   = col_lo + CHUNK * 4;          // one-past-last element col

    const bool has_one =
        ((unsigned)(c0 - col_lo) < (unsigned)(CHUNK * 4)) |
        ((unsigned)(c1 - col_lo) < (unsigned)(CHUNK * 4)) |
        ((unsigned)(c2 - col_lo) < (unsigned)(CHUNK * 4));

    int j = chunk_lo + threadIdx.x;
    const float4 z = make_float4(0.f, 0.f, 0.f, 0.f);

    if (!has_one) {
        // Hot path (~99.97% of blocks): pure streaming zero-fill.
        if (chunk_lo + CHUNK <= ROW_VEC) {
            #pragma unroll
            for (int it = 0; it < VPT; ++it, j += TPB)
                stcs4(&row_out[j], z);
        } else {
            #pragma unroll
            for (int it = 0; it < VPT; ++it, j += TPB)
                if (j < ROW_VEC) stcs4(&row_out[j], z);
        }
    } else {
        #pragma unroll
        for (int it = 0; it < VPT; ++it, j += TPB) {
            if (j < ROW_VEC) {
                const int base = j * 4;
                float4 v = z;
                int d;
                d = c0 - base; if ((unsigned)d < 4u) ((float*)&v)[d] = 1.0f;
                d = c1 - base; if ((unsigned)d < 4u) ((float*)&v)[d] = 1.0f;
                d = c2 - base; if ((unsigned)d < 4u) ((float*)&v)[d] = 1.0f;
                stcs4(&row_out[j], v);
            }
        }
    }
}

extern "C" void kernel_launch(void* const* d_in, const int* in_sizes, int n_in,
                              void* d_out, int out_size) {
    // Inputs per metadata order: z (f32, unused), hID (i32), rID (i32), tID (i32)
    const int* hID = (const int*)d_in[1];
    const int* rID = (const int*)d_in[2];
    const int* tID = (const int*)d_in[3];
    float* out = (float*)d_out;

    dim3 grid((ROW_VEC + CHUNK - 1) / CHUNK, BATCH);  // (25, 1024)
    fused_onehot_kernel<<<grid, TPB>>>(hID, rID, tID, out);
}